// round 1
// baseline (speedup 1.0000x reference)
#include <cuda_runtime.h>
#include <math.h>

#define NB 32
#define NS 64
#define NH 512
#define NA 128
#define NWIN 2016
#define NWPAD 2048
#define NLEV 7

// Scratch (static device globals — no allocation).
__device__ float g_table[NLEV * NB * NS * NH];   // ~29.4 MB, fits L2
__device__ float g_scores[NB * NWPAD];
__device__ float g_attn[NB * NWPAD];
__device__ int   g_win[NWPAD];                   // packed: s | e2<<8 | k<<16

// ---------------------------------------------------------------------------
// Window index table: widths w=2..64, starts s=0..64-w.
// F(w) = number of windows with width < w = (129-w)(w-2)/2.
__global__ void k_init_win() {
    int n = blockIdx.x * blockDim.x + threadIdx.x;
    if (n >= NWPAD) return;
    int nn = n < NWIN ? n : NWIN - 1;
    int w = 2;
#pragma unroll 1
    for (int ww = 3; ww <= NS; ww++) {
        int F = (129 - ww) * (ww - 2) / 2;
        if (F <= nn) w = ww;
    }
    int Fw = (129 - w) * (w - 2) / 2;
    int s = nn - Fw;
    int k = 31 - __clz(w);          // floor(log2(w))
    int e2 = s + w - (1 << k);      // second gather position (end - 2^k)
    g_win[n] = s | (e2 << 8) | (k << 16);
}

// ---------------------------------------------------------------------------
// Sparse table build: M[k][i] = max over lstm[i : i+2^k] (clipped).
// Block = (h-chunk of 64, batch). All levels computed in smem, streamed out.
__global__ void __launch_bounds__(256) k_table(const float* __restrict__ lstm) {
    int b = blockIdx.y;
    int h0 = blockIdx.x * 64;
    __shared__ float buf[2][NS][64];
    int tid = threadIdx.x;

    for (int idx = tid; idx < NS * 64; idx += 256) {
        int i = idx >> 6, h = idx & 63;
        float v = lstm[(b * NS + i) * NH + h0 + h];
        buf[0][i][h] = v;
        g_table[((size_t)(0 * NB + b) * NS + i) * NH + h0 + h] = v;
    }
    __syncthreads();

    int cur = 0;
    for (int k = 1; k < NLEV; k++) {
        int half = 1 << (k - 1);
        int nxt = cur ^ 1;
        for (int idx = tid; idx < NS * 64; idx += 256) {
            int i = idx >> 6, h = idx & 63;
            float v = buf[cur][i][h];
            if (i + half < NS) v = fmaxf(v, buf[cur][i + half][h]);
            buf[nxt][i][h] = v;
            g_table[((size_t)(k * NB + b) * NS + i) * NH + h0 + h] = v;
        }
        __syncthreads();
        cur = nxt;
    }
}

// ---------------------------------------------------------------------------
// Score GEMM, fused pooled-gather:
// hid = relu(pooled @ W1 + b1); score = hid @ W2 + b2.
// Block: 64 windows x 128 ATT, K=512 in chunks of 32.
__global__ void __launch_bounds__(256) k_scores(
    const float* __restrict__ W1, const float* __restrict__ b1,
    const float* __restrict__ W2, const float* __restrict__ b2)
{
    int b  = blockIdx.y;
    int n0 = blockIdx.x * 64;
    __shared__ float sP[64][32];                    // pooled tile [m][kk]
    __shared__ __align__(16) float sW[32][128];     // W1 tile [kk][a]
    __shared__ int swin[64];

    int tid = threadIdx.x;
    int tx = tid & 31, ty = tid >> 5;

    if (tid < 64) {
        int n = n0 + tid;
        swin[tid] = g_win[n < NWIN ? n : NWIN - 1];
    }
    __syncthreads();

    float acc[8][4];
#pragma unroll
    for (int r = 0; r < 8; r++)
#pragma unroll
        for (int c = 0; c < 4; c++) acc[r][c] = 0.f;

    for (int kt = 0; kt < NH; kt += 32) {
        // W1 tile
        for (int idx = tid; idx < 32 * 128; idx += 256) {
            int r = idx >> 7, c = idx & 127;
            sW[r][c] = W1[(kt + r) * NA + c];
        }
        // pooled tile via 2 sparse-table gathers
        for (int idx = tid; idx < 64 * 32; idx += 256) {
            int m = idx >> 5, kk = idx & 31;
            int wi = swin[m];
            int s = wi & 255, e2 = (wi >> 8) & 255, k = wi >> 16;
            const float* base = g_table + (size_t)(k * NB + b) * NS * NH + kt + kk;
            sP[m][kk] = fmaxf(base[s * NH], base[e2 * NH]);
        }
        __syncthreads();

#pragma unroll
        for (int kk = 0; kk < 32; kk++) {
            float4 wv = *(const float4*)&sW[kk][tx * 4];
#pragma unroll
            for (int r = 0; r < 8; r++) {
                float p = sP[ty * 8 + r][kk];
                acc[r][0] = fmaf(p, wv.x, acc[r][0]);
                acc[r][1] = fmaf(p, wv.y, acc[r][1]);
                acc[r][2] = fmaf(p, wv.z, acc[r][2]);
                acc[r][3] = fmaf(p, wv.w, acc[r][3]);
            }
        }
        __syncthreads();
    }

    // Epilogue: relu + bias, dot with W2, warp-reduce over ATT (tx dimension).
    float4 bb = *(const float4*)&b1[tx * 4];
    float4 w2 = *(const float4*)&W2[tx * 4];
    float b2v = b2[0];
#pragma unroll
    for (int r = 0; r < 8; r++) {
        float h0v = fmaxf(acc[r][0] + bb.x, 0.f);
        float h1v = fmaxf(acc[r][1] + bb.y, 0.f);
        float h2v = fmaxf(acc[r][2] + bb.z, 0.f);
        float h3v = fmaxf(acc[r][3] + bb.w, 0.f);
        float part = h0v * w2.x + h1v * w2.y + h2v * w2.z + h3v * w2.w;
#pragma unroll
        for (int off = 16; off > 0; off >>= 1)
            part += __shfl_down_sync(0xffffffffu, part, off);
        if (tx == 0) {
            int n = n0 + ty * 8 + r;
            if (n < NWIN) g_scores[b * NWPAD + n] = part + b2v;
        }
    }
}

// ---------------------------------------------------------------------------
// Softmax over windows, per batch.
__global__ void __launch_bounds__(256) k_softmax() {
    int b = blockIdx.x;
    int tid = threadIdx.x;
    __shared__ float red[256];

    float mx = -1e30f;
    for (int n = tid; n < NWIN; n += 256)
        mx = fmaxf(mx, g_scores[b * NWPAD + n]);
    red[tid] = mx;
    __syncthreads();
    for (int s = 128; s > 0; s >>= 1) {
        if (tid < s) red[tid] = fmaxf(red[tid], red[tid + s]);
        __syncthreads();
    }
    mx = red[0];
    __syncthreads();

    float sum = 0.f;
    for (int n = tid; n < NWIN; n += 256) {
        float e = expf(g_scores[b * NWPAD + n] - mx);
        g_attn[b * NWPAD + n] = e;
        sum += e;
    }
    red[tid] = sum;
    __syncthreads();
    for (int s = 128; s > 0; s >>= 1) {
        if (tid < s) red[tid] += red[tid + s];
        __syncthreads();
    }
    float inv = 1.f / red[0];
    for (int n = tid; n < NWIN; n += 256)
        g_attn[b * NWPAD + n] *= inv;
}

// ---------------------------------------------------------------------------
// out[b][h] = sum_n attn[n] * max(T[k][s][h], T[k][e2][h])   (re-gather, L2 hits)
__global__ void __launch_bounds__(128) k_out(float* __restrict__ out) {
    int b = blockIdx.y;
    int h = blockIdx.x * 128 + threadIdx.x;
    int tid = threadIdx.x;
    __shared__ float sa[256];
    __shared__ int   swn[256];
    float acc = 0.f;

    for (int n0 = 0; n0 < NWIN; n0 += 256) {
        __syncthreads();
        int lim = min(256, NWIN - n0);
        for (int j = tid; j < lim; j += 128) {
            sa[j]  = g_attn[b * NWPAD + n0 + j];
            swn[j] = g_win[n0 + j];
        }
        __syncthreads();
        const float* tb = g_table + h;
#pragma unroll 4
        for (int j = 0; j < lim; j++) {
            int wi = swn[j];
            int s = wi & 255, e2 = (wi >> 8) & 255, k = wi >> 16;
            const float* base = tb + (size_t)(k * NB + b) * NS * NH;
            acc += sa[j] * fmaxf(base[s * NH], base[e2 * NH]);
        }
    }
    out[b * NH + h] = acc;
}

// ---------------------------------------------------------------------------
extern "C" void kernel_launch(void* const* d_in, const int* in_sizes, int n_in,
                              void* d_out, int out_size) {
    const float* lstm = (const float*)d_in[0];
    const float* W1   = (const float*)d_in[1];
    const float* b1   = (const float*)d_in[2];
    const float* W2   = (const float*)d_in[3];
    const float* b2   = (const float*)d_in[4];
    float* out = (float*)d_out;

    k_init_win<<<NWPAD / 256, 256>>>();
    k_table<<<dim3(NH / 64, NB), 256>>>(lstm);
    k_scores<<<dim3(NWPAD / 64, NB), 256>>>(W1, b1, W2, b2);
    k_softmax<<<NB, 256>>>();
    k_out<<<dim3(NH / 128, NB), 128>>>(out);
}

// round 3
// speedup vs baseline: 1.8310x; 1.8310x over previous
#include <cuda_runtime.h>
#include <cuda_bf16.h>
#include <cstdint>
#include <math.h>

#define NB 32
#define NS 64
#define NH 512
#define NA 128
#define NWIN 2016
#define NWPAD 2048
#define NLEV 7
#define MT 128          // windows per CTA tile
#define KT 32           // K per k-tile (bf16 elements)
#define NKT (NH / KT)   // 16 k-tiles
#define LDS_A 40        // padded row stride (bf16) -> 80B, conflict-free ldmatrix

// Scratch (static device globals — no allocation).
__device__ float g_table[NLEV * NB * NS * NH];   // ~29.4 MB, L2-resident
__device__ float g_scores[NB * NWPAD];
__device__ float g_attn[NB * NWPAD];
__device__ int   g_win[NWPAD];                   // packed: s | e2<<8 | k<<16

// ---------------------------------------------------------------------------
__device__ __forceinline__ uint32_t smem_u32(const void* p) {
    uint32_t a;
    asm("{ .reg .u64 t; cvta.to.shared.u64 t, %1; cvt.u32.u64 %0, t; }" : "=r"(a) : "l"(p));
    return a;
}
#define LDSM_X4(r0, r1, r2, r3, a) \
    asm volatile("ldmatrix.sync.aligned.m8n8.x4.shared.b16 {%0,%1,%2,%3}, [%4];" \
        : "=r"(r0), "=r"(r1), "=r"(r2), "=r"(r3) : "r"(a))

__device__ __forceinline__ void mma_bf16(float* c, const uint32_t* a, const uint32_t* b) {
    asm volatile(
        "mma.sync.aligned.m16n8k16.row.col.f32.bf16.bf16.f32 "
        "{%0,%1,%2,%3}, {%4,%5,%6,%7}, {%8,%9}, {%0,%1,%2,%3};"
        : "+f"(c[0]), "+f"(c[1]), "+f"(c[2]), "+f"(c[3])
        : "r"(a[0]), "r"(a[1]), "r"(a[2]), "r"(a[3]), "r"(b[0]), "r"(b[1]));
}

// ---------------------------------------------------------------------------
__global__ void k_init_win() {
    int n = blockIdx.x * blockDim.x + threadIdx.x;
    if (n >= NWPAD) return;
    int nn = n < NWIN ? n : NWIN - 1;
    int w = 2;
#pragma unroll 1
    for (int ww = 3; ww <= NS; ww++) {
        int F = (129 - ww) * (ww - 2) / 2;
        if (F <= nn) w = ww;
    }
    int Fw = (129 - w) * (w - 2) / 2;
    int s = nn - Fw;
    int k = 31 - __clz(w);
    int e2 = s + w - (1 << k);
    g_win[n] = s | (e2 << 8) | (k << 16);
}

// ---------------------------------------------------------------------------
__global__ void __launch_bounds__(256) k_table(const float* __restrict__ lstm) {
    int b = blockIdx.y;
    int h0 = blockIdx.x * 64;
    __shared__ float buf[2][NS][64];
    int tid = threadIdx.x;

    for (int idx = tid; idx < NS * 64; idx += 256) {
        int i = idx >> 6, h = idx & 63;
        float v = lstm[(b * NS + i) * NH + h0 + h];
        buf[0][i][h] = v;
        g_table[((size_t)(0 * NB + b) * NS + i) * NH + h0 + h] = v;
    }
    __syncthreads();
    int cur = 0;
    for (int k = 1; k < NLEV; k++) {
        int half = 1 << (k - 1);
        int nxt = cur ^ 1;
        for (int idx = tid; idx < NS * 64; idx += 256) {
            int i = idx >> 6, h = idx & 63;
            float v = buf[cur][i][h];
            if (i + half < NS) v = fmaxf(v, buf[cur][i + half][h]);
            buf[nxt][i][h] = v;
            g_table[((size_t)(k * NB + b) * NS + i) * NH + h0 + h] = v;
        }
        __syncthreads();
        cur = nxt;
    }
}

// ---------------------------------------------------------------------------
// Score kernel via warp-level bf16 mma.sync (HMMA), 3-pass hi/lo fp32 emulation.
// CTA: 128 windows x 128 ATT, K=512 in 16 tiles of 32.
// Warp grid 4x2 (m x n): warp tile 32 rows x 64 cols.
__global__ void __launch_bounds__(256, 2) k_scores_mma(
    const float* __restrict__ W1, const float* __restrict__ b1,
    const float* __restrict__ W2, const float* __restrict__ b2)
{
    __shared__ __align__(16) __nv_bfloat16 aHi[MT][LDS_A];
    __shared__ __align__(16) __nv_bfloat16 aLo[MT][LDS_A];
    __shared__ __align__(16) __nv_bfloat16 bHi[NA][LDS_A];
    __shared__ __align__(16) __nv_bfloat16 bLo[NA][LDS_A];
    __shared__ float sPart[2][MT];
    __shared__ float sb1[NA], sw2[NA];
    __shared__ int s_win[MT];

    int b  = blockIdx.y;
    int n0 = blockIdx.x * MT;
    int tid  = threadIdx.x;
    int wid  = tid >> 5, lane = tid & 31;
    int wm = wid & 3, wn = wid >> 2;      // 4 x 2 warp grid

    if (tid < MT) {
        int n = n0 + tid;
        s_win[tid] = g_win[n < NWIN ? n : NWIN - 1];
    }
    if (tid < NA) { sb1[tid] = b1[tid]; sw2[tid] = W2[tid]; }

    float acc[2][8][4];
#pragma unroll
    for (int mt = 0; mt < 2; mt++)
#pragma unroll
        for (int nt = 0; nt < 8; nt++)
#pragma unroll
            for (int j = 0; j < 4; j++) acc[mt][nt][j] = 0.f;

    __syncthreads();

    // ldmatrix lane addresses (byte offsets within a tile)
    // A (m16k16): row = lane&15, colblk = lane>>4
    uint32_t aRow = (uint32_t)(lane & 15);
    uint32_t aCol = (uint32_t)(lane >> 4) * 16u;
    // B (two n8k16 tiles): n = (lane&7) + ((lane>>4)<<3), colblk = (lane>>3)&1
    uint32_t bRow = (uint32_t)((lane & 7) + ((lane >> 4) << 3));
    uint32_t bCol = (uint32_t)((lane >> 3) & 1) * 16u;

    uint32_t aHiBase = smem_u32(&aHi[0][0]), aLoBase = smem_u32(&aLo[0][0]);
    uint32_t bHiBase = smem_u32(&bHi[0][0]), bLoBase = smem_u32(&bLo[0][0]);

    for (int t = 0; t < NKT; t++) {
        int th0 = t * KT;

        // ---- fill A (pooled gather -> bf16 hi/lo). p: m = p>>4, q = p&15 (k pair)
        for (int p = tid; p < MT * 16; p += 256) {
            int m = p >> 4, q = p & 15;
            int wi = s_win[m];
            int s = wi & 255, e2 = (wi >> 8) & 255, k = wi >> 16;
            const float* tb = g_table + ((k * NB + b) * NS) * NH + th0 + 2 * q;
            float v0 = fmaxf(tb[s * NH],     tb[e2 * NH]);
            float v1 = fmaxf(tb[s * NH + 1], tb[e2 * NH + 1]);
            __nv_bfloat16 h0 = __float2bfloat16(v0), h1 = __float2bfloat16(v1);
            __nv_bfloat16 l0 = __float2bfloat16(v0 - __bfloat162float(h0));
            __nv_bfloat16 l1 = __float2bfloat16(v1 - __bfloat162float(h1));
            __nv_bfloat162 ph = __nv_bfloat162(h0, h1), pl = __nv_bfloat162(l0, l1);
            *(uint32_t*)&aHi[m][2 * q] = *(uint32_t*)&ph;
            *(uint32_t*)&aLo[m][2 * q] = *(uint32_t*)&pl;
        }
        // ---- fill B = W1^T tile. p: q = p>>7 (k pair), n = p&127 (coalesced)
        for (int p = tid; p < 16 * NA; p += 256) {
            int q = p >> 7, n = p & 127;
            float v0 = W1[(th0 + 2 * q) * NA + n];
            float v1 = W1[(th0 + 2 * q + 1) * NA + n];
            __nv_bfloat16 h0 = __float2bfloat16(v0), h1 = __float2bfloat16(v1);
            __nv_bfloat16 l0 = __float2bfloat16(v0 - __bfloat162float(h0));
            __nv_bfloat16 l1 = __float2bfloat16(v1 - __bfloat162float(h1));
            __nv_bfloat162 ph = __nv_bfloat162(h0, h1), pl = __nv_bfloat162(l0, l1);
            *(uint32_t*)&bHi[n][2 * q] = *(uint32_t*)&ph;
            *(uint32_t*)&bLo[n][2 * q] = *(uint32_t*)&pl;
        }
        __syncthreads();

        // ---- compute: 2 k-steps of 16
#pragma unroll
        for (int ks = 0; ks < 2; ks++) {
            uint32_t kOff = (uint32_t)ks * 32u;  // 16 bf16 = 32 bytes

            uint32_t Ah[2][4], Al[2][4];
#pragma unroll
            for (int mt = 0; mt < 2; mt++) {
                uint32_t row = (uint32_t)(wm * 32 + mt * 16) + aRow;
                uint32_t off = row * (LDS_A * 2) + kOff + aCol;
                LDSM_X4(Ah[mt][0], Ah[mt][1], Ah[mt][2], Ah[mt][3], aHiBase + off);
                LDSM_X4(Al[mt][0], Al[mt][1], Al[mt][2], Al[mt][3], aLoBase + off);
            }
#pragma unroll
            for (int np = 0; np < 4; np++) {   // pairs of n8 tiles
                uint32_t nrow = (uint32_t)(wn * 64 + np * 16) + bRow;
                uint32_t off = nrow * (LDS_A * 2) + kOff + bCol;
                uint32_t Bh[4], Bl[4];
                LDSM_X4(Bh[0], Bh[1], Bh[2], Bh[3], bHiBase + off);
                LDSM_X4(Bl[0], Bl[1], Bl[2], Bl[3], bLoBase + off);
#pragma unroll
                for (int mt = 0; mt < 2; mt++) {
#pragma unroll
                    for (int h = 0; h < 2; h++) {
                        int nt = np * 2 + h;
                        mma_bf16(acc[mt][nt], Ah[mt], &Bh[h * 2]);
                        mma_bf16(acc[mt][nt], Ah[mt], &Bl[h * 2]);
                        mma_bf16(acc[mt][nt], Al[mt], &Bh[h * 2]);
                    }
                }
            }
        }
        __syncthreads();
    }

    // ---- epilogue: relu(acc + b1) dot W2, reduce over n
    int gq = lane >> 2;   // row group 0..7
    int gr = lane & 3;    // col group
#pragma unroll
    for (int mt = 0; mt < 2; mt++) {
        float p0 = 0.f, p1 = 0.f;
#pragma unroll
        for (int nt = 0; nt < 8; nt++) {
            int col = wn * 64 + nt * 8 + gr * 2;
            float b1a = sb1[col], b1b = sb1[col + 1];
            float w2a = sw2[col], w2b = sw2[col + 1];
            p0 = fmaf(fmaxf(acc[mt][nt][0] + b1a, 0.f), w2a, p0);
            p0 = fmaf(fmaxf(acc[mt][nt][1] + b1b, 0.f), w2b, p0);
            p1 = fmaf(fmaxf(acc[mt][nt][2] + b1a, 0.f), w2a, p1);
            p1 = fmaf(fmaxf(acc[mt][nt][3] + b1b, 0.f), w2b, p1);
        }
#pragma unroll
        for (int off = 1; off <= 2; off <<= 1) {
            p0 += __shfl_xor_sync(0xffffffffu, p0, off);
            p1 += __shfl_xor_sync(0xffffffffu, p1, off);
        }
        if (gr == 0) {
            int row = wm * 32 + mt * 16 + gq;
            sPart[wn][row]     = p0;
            sPart[wn][row + 8] = p1;
        }
    }
    __syncthreads();
    if (tid < MT) {
        int n = n0 + tid;
        if (n < NWIN)
            g_scores[b * NWPAD + n] = sPart[0][tid] + sPart[1][tid] + b2[0];
    }
}

// ---------------------------------------------------------------------------
__global__ void __launch_bounds__(256) k_softmax() {
    int b = blockIdx.x;
    int tid = threadIdx.x;
    __shared__ float red[256];

    float mx = -1e30f;
    for (int n = tid; n < NWIN; n += 256)
        mx = fmaxf(mx, g_scores[b * NWPAD + n]);
    red[tid] = mx;
    __syncthreads();
    for (int s = 128; s > 0; s >>= 1) {
        if (tid < s) red[tid] = fmaxf(red[tid], red[tid + s]);
        __syncthreads();
    }
    mx = red[0];
    __syncthreads();
    float sum = 0.f;
    for (int n = tid; n < NWIN; n += 256) {
        float e = expf(g_scores[b * NWPAD + n] - mx);
        g_attn[b * NWPAD + n] = e;
        sum += e;
    }
    red[tid] = sum;
    __syncthreads();
    for (int s = 128; s > 0; s >>= 1) {
        if (tid < s) red[tid] += red[tid + s];
        __syncthreads();
    }
    float inv = 1.f / red[0];
    for (int n = tid; n < NWIN; n += 256)
        g_attn[b * NWPAD + n] *= inv;
}

// ---------------------------------------------------------------------------
__global__ void __launch_bounds__(128) k_out(float* __restrict__ out) {
    int b = blockIdx.y;
    int h = blockIdx.x * 128 + threadIdx.x;
    int tid = threadIdx.x;
    __shared__ float sa[256];
    __shared__ int   swn[256];
    float acc = 0.f;

    for (int n0 = 0; n0 < NWIN; n0 += 256) {
        __syncthreads();
        int lim = min(256, NWIN - n0);
        for (int j = tid; j < lim; j += 128) {
            sa[j]  = g_attn[b * NWPAD + n0 + j];
            swn[j] = g_win[n0 + j];
        }
        __syncthreads();
        const float* tb = g_table + h;
#pragma unroll 4
        for (int j = 0; j < lim; j++) {
            int wi = swn[j];
            int s = wi & 255, e2 = (wi >> 8) & 255, k = wi >> 16;
            const float* base = tb + (size_t)(k * NB + b) * NS * NH;
            acc += sa[j] * fmaxf(base[s * NH], base[e2 * NH]);
        }
    }
    out[b * NH + h] = acc;
}

// ---------------------------------------------------------------------------
extern "C" void kernel_launch(void* const* d_in, const int* in_sizes, int n_in,
                              void* d_out, int out_size) {
    const float* lstm = (const float*)d_in[0];
    const float* W1   = (const float*)d_in[1];
    const float* b1   = (const float*)d_in[2];
    const float* W2   = (const float*)d_in[3];
    const float* b2   = (const float*)d_in[4];
    float* out = (float*)d_out;

    k_init_win<<<NWPAD / 256, 256>>>();
    k_table<<<dim3(NH / 64, NB), 256>>>(lstm);
    k_scores_mma<<<dim3(NWPAD / MT, NB), 256>>>(W1, b1, W2, b2);
    k_softmax<<<NB, 256>>>();
    k_out<<<dim3(NH / 128, NB), 128>>>(out);
}